// round 16
// baseline (speedup 1.0000x reference)
#include <cuda_runtime.h>
#include <cuda_fp16.h>
#include <cstdint>

// ---------------- problem constants ----------------
#define S_    2048
#define N_    8
#define E_    512
#define C_    1024
#define G_    32
#define CG_   32
#define TOK_  (S_ * N_)          // 16384 tokens
#define NGRP  (TOK_ * G_)        // 524288 groups
#define LN_EPS 1e-5f

// GEMM tiling (mma.sync path — tcgen05 unavailable on this toolchain)
#define BM 128
#define BN 128
#define BK 32
#define NCHUNK1 32                // gemm1: 2 fp16 split segments x (512/32)
#define NCHUNK2 32                // gemm2: K=1024 / 32
#define ASTRIDE 40                // smem row stride in fp16 elems (80 B)

// refinement trigger: fp16-2seg logit error bound ~8e-4 max; 5x headroom
#define REFINE_THR 4e-3f

// ---------------- scratch (device globals) --------
__device__ float  g_logits[(size_t)TOK_ * C_];         // 64 MB
__device__ __half g_Ahi[(size_t)TOK_ * E_];            // 16 MB
__device__ __half g_Alo[(size_t)TOK_ * E_];            // 16 MB
__device__ __half g_Bhi[(size_t)C_ * E_];              // 1 MB
__device__ __half g_sampH[(size_t)TOK_ * C_];          // 32 MB (fp16 sampled)
__device__ __half g_W2h[(size_t)E_ * C_];              // 1 MB  (fp16 W2, [e][c])
__device__ float  g_posPre[(size_t)TOK_ * E_];         // 32 MB (pre-LN projection)
__device__ int    g_refCnt;                            // refine-list counter
__device__ int    g_refList[NGRP];                     // 2 MB (worst case)

// ---------------- helpers ----------------
__device__ __forceinline__ uint32_t smem_u32(const void* p) {
    uint32_t a;
    asm("{ .reg .u64 t; cvta.to.shared.u64 t, %1; cvt.u32.u64 %0, t; }"
        : "=r"(a) : "l"(p));
    return a;
}
__device__ __forceinline__ void cp16(uint32_t saddr, const void* gptr) {
    asm volatile("cp.async.cg.shared.global [%0], [%1], 16;"
                 :: "r"(saddr), "l"(gptr) : "memory");
}
__device__ __forceinline__ void ldm_x4(uint32_t* r, uint32_t addr) {
    asm volatile("ldmatrix.sync.aligned.m8n8.x4.shared.b16 {%0,%1,%2,%3}, [%4];"
                 : "=r"(r[0]), "=r"(r[1]), "=r"(r[2]), "=r"(r[3]) : "r"(addr));
}
__device__ __forceinline__ void mma16816(float* c, const uint32_t* a, const uint32_t* b) {
    asm volatile(
        "mma.sync.aligned.m16n8k16.row.col.f32.f16.f16.f32 "
        "{%0,%1,%2,%3}, {%4,%5,%6,%7}, {%8,%9}, {%0,%1,%2,%3};"
        : "+f"(c[0]), "+f"(c[1]), "+f"(c[2]), "+f"(c[3])
        : "r"(a[0]), "r"(a[1]), "r"(a[2]), "r"(a[3]), "r"(b[0]), "r"(b[1]));
}
__device__ __forceinline__ uint32_t h2_bits(__half2 h) {
    return *reinterpret_cast<uint32_t*>(&h);
}

// ---------------- kernel 0z: reset refine counter --------------------------
__global__ void zero_k() {
    if (threadIdx.x == 0 && blockIdx.x == 0) g_refCnt = 0;
}

// ---------------- kernel 0a: fp32 -> (fp16 hi, fp16 lo) split of x --------
__global__ void split_x_k(const float* __restrict__ in) {
    int i = blockIdx.x * 256 + threadIdx.x;
    if (i < TOK_ * E_ / 4) {
        float4 v = ((const float4*)in)[i];
        __half h0 = __float2half_rn(v.x), h1 = __float2half_rn(v.y);
        __half h2 = __float2half_rn(v.z), h3 = __float2half_rn(v.w);
        __half2 hi01, hi23, lo01, lo23;
        hi01.x = h0; hi01.y = h1; hi23.x = h2; hi23.y = h3;
        lo01.x = __float2half_rn(v.x - __half2float(h0));
        lo01.y = __float2half_rn(v.y - __half2float(h1));
        lo23.x = __float2half_rn(v.z - __half2float(h2));
        lo23.y = __float2half_rn(v.w - __half2float(h3));
        ((__half2*)g_Ahi)[i * 2]     = hi01;
        ((__half2*)g_Ahi)[i * 2 + 1] = hi23;
        ((__half2*)g_Alo)[i * 2]     = lo01;
        ((__half2*)g_Alo)[i * 2 + 1] = lo23;
    }
}
// ---------------- kernel 0b: W1 -> fp16 ------------------------------------
__global__ void split_w_k(const float* __restrict__ in) {
    int i = blockIdx.x * 256 + threadIdx.x;
    if (i < C_ * E_ / 4) {
        float4 v = ((const float4*)in)[i];
        __half2 hi01, hi23;
        hi01.x = __float2half_rn(v.x); hi01.y = __float2half_rn(v.y);
        hi23.x = __float2half_rn(v.z); hi23.y = __float2half_rn(v.w);
        ((__half2*)g_Bhi)[i * 2]     = hi01;
        ((__half2*)g_Bhi)[i * 2 + 1] = hi23;
    }
}
// ---------------- kernel 0c: W2 -> fp16 (layout kept: [e][c]) --------------
__global__ void w2h_k(const float* __restrict__ in) {
    int i = blockIdx.x * 256 + threadIdx.x;
    if (i < E_ * C_ / 4) {
        float4 v = ((const float4*)in)[i];
        __half2 h01, h23;
        h01.x = __float2half_rn(v.x); h01.y = __float2half_rn(v.y);
        h23.x = __float2half_rn(v.z); h23.y = __float2half_rn(v.w);
        ((__half2*)g_W2h)[i * 2]     = h01;
        ((__half2*)g_W2h)[i * 2 + 1] = h23;
    }
}

// ---------------- kernel 1: fp16 split-GEMM  logits = 3(xW1^T + b1) + coff -
// (proven 123us version — skinny epilogue, NO fusion)
__global__ void __launch_bounds__(256, 2)
gemm_mma(const float* __restrict__ b1, const float* __restrict__ coff)
{
    __shared__ __align__(16) __half sA[2][BM * ASTRIDE];
    __shared__ __align__(16) __half sB[2][BN * ASTRIDE];

    const int tid  = threadIdx.x;
    const int lane = tid & 31;
    const int wid  = tid >> 5;
    const int wm   = (wid & 3) * 32;
    const int wn   = (wid >> 2) * 64;
    const int m0   = blockIdx.y * BM;
    const int n0   = blockIdx.x * BN;

    const uint32_t aBase[2] = { smem_u32(&sA[0][0]), smem_u32(&sA[1][0]) };
    const uint32_t bBase[2] = { smem_u32(&sB[0][0]), smem_u32(&sB[1][0]) };

    const int lrow0 = tid >> 2,         lcg0 = (tid & 3);
    const int lrow1 = (tid + 256) >> 2, lcg1 = ((tid + 256) & 3);

    auto issue_loads = [&](int kc) {
        const int b   = kc & 1;
        const int seg = kc >> 4;
        const __half* Asrc = seg ? g_Alo : g_Ahi;
        const int kcol = (kc & 15) * BK;
        cp16(aBase[b] + (uint32_t)(lrow0 * ASTRIDE + lcg0 * 8) * 2,
             Asrc + (size_t)(m0 + lrow0) * E_ + kcol + lcg0 * 8);
        cp16(aBase[b] + (uint32_t)(lrow1 * ASTRIDE + lcg1 * 8) * 2,
             Asrc + (size_t)(m0 + lrow1) * E_ + kcol + lcg1 * 8);
        cp16(bBase[b] + (uint32_t)(lrow0 * ASTRIDE + lcg0 * 8) * 2,
             g_Bhi + (size_t)(n0 + lrow0) * E_ + kcol + lcg0 * 8);
        cp16(bBase[b] + (uint32_t)(lrow1 * ASTRIDE + lcg1 * 8) * 2,
             g_Bhi + (size_t)(n0 + lrow1) * E_ + kcol + lcg1 * 8);
        asm volatile("cp.async.commit_group;" ::: "memory");
    };

    float acc[2][8][4];
    #pragma unroll
    for (int i = 0; i < 2; i++)
        #pragma unroll
        for (int j = 0; j < 8; j++)
            #pragma unroll
            for (int r = 0; r < 4; r++) acc[i][j][r] = 0.0f;

    issue_loads(0);

    for (int kc = 0; kc < NCHUNK1; kc++) {
        const int b = kc & 1;
        if (kc + 1 < NCHUNK1) {
            issue_loads(kc + 1);
            asm volatile("cp.async.wait_group 1;" ::: "memory");
        } else {
            asm volatile("cp.async.wait_group 0;" ::: "memory");
        }
        __syncthreads();

        #pragma unroll
        for (int ks = 0; ks < 2; ks++) {
            uint32_t afr[2][4];
            #pragma unroll
            for (int i = 0; i < 2; i++) {
                int row  = wm + i * 16 + (lane & 7) + ((lane >> 3) & 1) * 8;
                int half = lane >> 4;
                ldm_x4(afr[i], aBase[b] + row * (ASTRIDE * 2) + ks * 32 + half * 16);
            }
            uint32_t bfr[8][2];
            #pragma unroll
            for (int bj = 0; bj < 4; bj++) {
                int row  = wn + bj * 16 + (lane & 7) + (lane >> 4) * 8;
                int half = (lane >> 3) & 1;
                uint32_t q[4];
                ldm_x4(q, bBase[b] + row * (ASTRIDE * 2) + ks * 32 + half * 16);
                bfr[bj * 2][0] = q[0];     bfr[bj * 2][1] = q[1];
                bfr[bj * 2 + 1][0] = q[2]; bfr[bj * 2 + 1][1] = q[3];
            }
            #pragma unroll
            for (int i = 0; i < 2; i++)
                #pragma unroll
                for (int j = 0; j < 8; j++)
                    mma16816(acc[i][j], afr[i], bfr[j]);
        }
        __syncthreads();
    }

    const int gp   = lane >> 2;
    const int tid4 = lane & 3;
    #pragma unroll
    for (int j = 0; j < 8; j++) {
        const int n = n0 + wn + j * 8 + tid4 * 2;
        const float c0 = fmaf(3.0f, __ldg(&b1[n + 0]), __ldg(&coff[n + 0]));
        const float c1 = fmaf(3.0f, __ldg(&b1[n + 1]), __ldg(&coff[n + 1]));
        #pragma unroll
        for (int i = 0; i < 2; i++) {
            const int mrow = m0 + wm + i * 16 + gp;
            float2 v0, v1;
            v0.x = fmaf(3.0f, acc[i][j][0], c0);
            v0.y = fmaf(3.0f, acc[i][j][1], c1);
            v1.x = fmaf(3.0f, acc[i][j][2], c0);
            v1.y = fmaf(3.0f, acc[i][j][3], c1);
            *(float2*)&g_logits[(size_t)mrow * C_ + n]       = v0;
            *(float2*)&g_logits[(size_t)(mrow + 8) * C_ + n] = v1;
        }
    }
}

// ---------------- kernel 2: thread-per-group softmax + sampling ------------
// One thread owns one group (32 classes): all reductions are thread-local
// register arithmetic. Near-tie groups are appended to a refine list and
// fixed up by refine_k (warp-per-group, exact fp32 chain).
__global__ void __launch_bounds__(256)
samp_k(const float* __restrict__ g1, const float* __restrict__ g2,
       const float* __restrict__ wI, const float* __restrict__ uI,
       float* __restrict__ oSamp, float* __restrict__ oSoft)
{
    const int gi = blockIdx.x * 256 + threadIdx.x;   // group 0..NGRP-1
    if (gi >= NGRP) return;
    const size_t base = (size_t)gi * CG_;

    // ---- load 32 logits ----
    float v[32];
    {
        const float4* v4 = (const float4*)(g_logits + base);
        #pragma unroll
        for (int k = 0; k < 8; k++) {
            float4 a = v4[k];
            v[k * 4 + 0] = a.x; v[k * 4 + 1] = a.y;
            v[k * 4 + 2] = a.z; v[k * 4 + 3] = a.w;
        }
    }

    // update step preserving "first wins ties" (strict >, ascending n)
    auto upd = [](float& bv, float& sec, int& bi, float z, int n) {
        if (z > bv) { sec = bv; bv = z; bi = n; }
        else        { sec = fmaxf(sec, z); }
    };
    // merge two ascending chains, lowest-index tie rule
    auto merge = [](float bvA, float secA, int biA,
                    float bvB, float secB, int biB,
                    float& bv, float& sec, int& bi) {
        if (bvB > bvA || (bvB == bvA && biB < biA)) {
            bv = bvB; bi = biB; sec = fmaxf(bvA, secB);
        } else {
            bv = bvA; bi = biA; sec = fmaxf(bvB, secA);
        }
    };

    // ---- draw 1 ----
    float bv1, sec1; int bi1;
    {
        const float4* p = (const float4*)(g1 + base);
        float bvA = -3.4e38f, secA = -3.4e38f; int biA = 0;
        float bvB = -3.4e38f, secB = -3.4e38f; int biB = 0;
        #pragma unroll
        for (int k = 0; k < 8; k += 2) {
            float4 a = __ldg(&p[k]);
            upd(bvA, secA, biA, v[k * 4 + 0] + a.x, k * 4 + 0);
            upd(bvA, secA, biA, v[k * 4 + 1] + a.y, k * 4 + 1);
            upd(bvA, secA, biA, v[k * 4 + 2] + a.z, k * 4 + 2);
            upd(bvA, secA, biA, v[k * 4 + 3] + a.w, k * 4 + 3);
            float4 b = __ldg(&p[k + 1]);
            upd(bvB, secB, biB, v[k * 4 + 4] + b.x, k * 4 + 4);
            upd(bvB, secB, biB, v[k * 4 + 5] + b.y, k * 4 + 5);
            upd(bvB, secB, biB, v[k * 4 + 6] + b.z, k * 4 + 6);
            upd(bvB, secB, biB, v[k * 4 + 7] + b.w, k * 4 + 7);
        }
        merge(bvA, secA, biA, bvB, secB, biB, bv1, sec1, bi1);
    }
    // ---- draw 2 ----
    float bv2, sec2; int bi2;
    {
        const float4* p = (const float4*)(g2 + base);
        float bvA = -3.4e38f, secA = -3.4e38f; int biA = 0;
        float bvB = -3.4e38f, secB = -3.4e38f; int biB = 0;
        #pragma unroll
        for (int k = 0; k < 8; k += 2) {
            float4 a = __ldg(&p[k]);
            upd(bvA, secA, biA, v[k * 4 + 0] + a.x, k * 4 + 0);
            upd(bvA, secA, biA, v[k * 4 + 1] + a.y, k * 4 + 1);
            upd(bvA, secA, biA, v[k * 4 + 2] + a.z, k * 4 + 2);
            upd(bvA, secA, biA, v[k * 4 + 3] + a.w, k * 4 + 3);
            float4 b = __ldg(&p[k + 1]);
            upd(bvB, secB, biB, v[k * 4 + 4] + b.x, k * 4 + 4);
            upd(bvB, secB, biB, v[k * 4 + 5] + b.y, k * 4 + 5);
            upd(bvB, secB, biB, v[k * 4 + 6] + b.z, k * 4 + 6);
            upd(bvB, secB, biB, v[k * 4 + 7] + b.w, k * 4 + 7);
        }
        merge(bvA, secA, biA, bvB, secB, biB, bv2, sec2, bi2);
    }

    // ---- near-tie groups -> refine list (fixed up by refine_k) ----
    if ((bv1 - sec1) < REFINE_THR || (bv2 - sec2) < REFINE_THR) {
        int slot = atomicAdd(&g_refCnt, 1);
        g_refList[slot] = gi;
    }

    // ---- softmax (exact max; 4-chain trees) ----
    {
        float t0 = v[0], t1 = v[1], t2 = v[2], t3 = v[3];
        #pragma unroll
        for (int k = 4; k < 32; k += 4) {
            t0 = fmaxf(t0, v[k]);     t1 = fmaxf(t1, v[k + 1]);
            t2 = fmaxf(t2, v[k + 2]); t3 = fmaxf(t3, v[k + 3]);
        }
        float mx = fmaxf(fmaxf(t0, t1), fmaxf(t2, t3));
        float s0 = 0.f, s1 = 0.f, s2 = 0.f, s3 = 0.f;
        #pragma unroll
        for (int k = 0; k < 32; k += 4) {
            v[k]     = __expf(v[k] - mx);     s0 += v[k];
            v[k + 1] = __expf(v[k + 1] - mx); s1 += v[k + 1];
            v[k + 2] = __expf(v[k + 2] - mx); s2 += v[k + 2];
            v[k + 3] = __expf(v[k + 3] - mx); s3 += v[k + 3];
        }
        float inv = 1.0f / ((s0 + s1) + (s2 + s3));
        float4* o4 = (float4*)(oSoft + base);
        #pragma unroll
        for (int k = 0; k < 8; k++) {
            float4 w4;
            w4.x = v[k * 4 + 0] * inv; w4.y = v[k * 4 + 1] * inv;
            w4.z = v[k * 4 + 2] * inv; w4.w = v[k * 4 + 3] * inv;
            o4[k] = w4;
        }
    }

    // ---- sampled (provisional for refined groups; overwritten later) ----
    {
        const float wv = __ldg(&wI[gi]);
        const float uv = __ldg(&uI[gi]);
        const float cwi = (uv < 1.0f) ? wv : 1.0f;
        const float cwj = (uv < 1.0f) ? (1.0f - wv) : 0.0f;

        float4* o4 = (float4*)(oSamp + base);
        uint4*  h4 = (uint4*)(g_sampH + base);   // 8 halves per uint4
        #pragma unroll
        for (int k = 0; k < 4; k++) {
            float sp[8];
            #pragma unroll
            for (int j = 0; j < 8; j++) {
                int n = k * 8 + j;
                sp[j] = ((n == bi1) ? cwi : 0.f) + ((n == bi2) ? cwj : 0.f);
            }
            float4 f0, f1;
            f0.x = sp[0]; f0.y = sp[1]; f0.z = sp[2]; f0.w = sp[3];
            f1.x = sp[4]; f1.y = sp[5]; f1.z = sp[6]; f1.w = sp[7];
            o4[k * 2]     = f0;
            o4[k * 2 + 1] = f1;
            __half2 h0 = __floats2half2_rn(sp[0], sp[1]);
            __half2 h1 = __floats2half2_rn(sp[2], sp[3]);
            __half2 h2 = __floats2half2_rn(sp[4], sp[5]);
            __half2 h3 = __floats2half2_rn(sp[6], sp[7]);
            uint4 hv;
            hv.x = h2_bits(h0); hv.y = h2_bits(h1);
            hv.z = h2_bits(h2); hv.w = h2_bits(h3);
            h4[k] = hv;
        }
    }
}

// ---------------- warp helper (refinement path only) ----------------------
__device__ __forceinline__ int warp_argmax(float z, int lane) {
    float bv = z; int bi = lane;
    #pragma unroll
    for (int off = 16; off; off >>= 1) {
        float ov = __shfl_xor_sync(0xffffffffu, bv, off);
        int   oi = __shfl_xor_sync(0xffffffffu, bi, off);
        if (ov > bv || (ov == bv && oi < bi)) { bv = ov; bi = oi; }
    }
    return bi;
}

// ---------------- kernel 2b: exact refinement (warp per listed group) ------
__global__ void __launch_bounds__(256)
refine_k(const float* __restrict__ g1, const float* __restrict__ g2,
         const float* __restrict__ wI, const float* __restrict__ uI,
         const float* __restrict__ x,  const float* __restrict__ W1,
         const float* __restrict__ b1, const float* __restrict__ coff,
         float* __restrict__ oSamp)
{
    const int lane = threadIdx.x & 31;
    const int gw   = (blockIdx.x * blockDim.x + threadIdx.x) >> 5;
    const int nW   = (gridDim.x * blockDim.x) >> 5;
    const int cnt  = g_refCnt;

    for (int i = gw; i < cnt; i += nW) {
        const int gi = g_refList[i];
        const int t  = gi >> 5;          // G_ == 32
        const int g  = gi & 31;
        const int cls = g * CG_ + lane;

        // exact sequential-fmaf fp32 chain (k ascending) — bit-identical to
        // the proven reference numerics
        const float4* x4 = (const float4*)(x + (size_t)t * E_);
        const float4* w4 = (const float4*)(W1 + (size_t)cls * E_);
        float acc = 0.f;
        #pragma unroll 4
        for (int k = 0; k < E_ / 4; k++) {
            float4 a = __ldg(&x4[k]);
            float4 b = __ldg(&w4[k]);
            acc = fmaf(a.x, b.x, acc);
            acc = fmaf(a.y, b.y, acc);
            acc = fmaf(a.z, b.z, acc);
            acc = fmaf(a.w, b.w, acc);
        }
        float cb = fmaf(3.0f, __ldg(&b1[cls]), __ldg(&coff[cls]));
        float vr = fmaf(3.0f, acc, cb);

        const size_t idx = (size_t)gi * CG_ + lane;
        int i1 = warp_argmax(vr + __ldg(&g1[idx]), lane);
        int i2 = warp_argmax(vr + __ldg(&g2[idx]), lane);

        const float wv = __ldg(&wI[gi]);
        const float uv = __ldg(&uI[gi]);
        const float cwi = (uv < 1.0f) ? wv : 1.0f;
        const float cwj = (uv < 1.0f) ? (1.0f - wv) : 0.0f;

        float val = 0.0f;
        if (lane == i1) val += cwi;
        if (lane == i2) val += cwj;
        oSamp[idx]   = val;
        g_sampH[idx] = __float2half_rn(val);
    }
}

// ---------------- kernel 3: fp16 GEMM  posPre = sampH @ W2h^T + b2 ---------
__global__ void __launch_bounds__(256, 2)
gemm2_mma(const float* __restrict__ b2)
{
    __shared__ __align__(16) __half sA[2][BM * ASTRIDE];
    __shared__ __align__(16) __half sB[2][BN * ASTRIDE];

    const int tid  = threadIdx.x;
    const int lane = tid & 31;
    const int wid  = tid >> 5;
    const int wm   = (wid & 3) * 32;
    const int wn   = (wid >> 2) * 64;
    const int m0   = blockIdx.y * BM;
    const int n0   = blockIdx.x * BN;

    const uint32_t aBase[2] = { smem_u32(&sA[0][0]), smem_u32(&sA[1][0]) };
    const uint32_t bBase[2] = { smem_u32(&sB[0][0]), smem_u32(&sB[1][0]) };

    const int lrow0 = tid >> 2,         lcg0 = (tid & 3);
    const int lrow1 = (tid + 256) >> 2, lcg1 = ((tid + 256) & 3);

    auto issue_loads = [&](int kc) {
        const int b    = kc & 1;
        const int kcol = kc * BK;
        cp16(aBase[b] + (uint32_t)(lrow0 * ASTRIDE + lcg0 * 8) * 2,
             g_sampH + (size_t)(m0 + lrow0) * C_ + kcol + lcg0 * 8);
        cp16(aBase[b] + (uint32_t)(lrow1 * ASTRIDE + lcg1 * 8) * 2,
             g_sampH + (size_t)(m0 + lrow1) * C_ + kcol + lcg1 * 8);
        cp16(bBase[b] + (uint32_t)(lrow0 * ASTRIDE + lcg0 * 8) * 2,
             g_W2h + (size_t)(n0 + lrow0) * C_ + kcol + lcg0 * 8);
        cp16(bBase[b] + (uint32_t)(lrow1 * ASTRIDE + lcg1 * 8) * 2,
             g_W2h + (size_t)(n0 + lrow1) * C_ + kcol + lcg1 * 8);
        asm volatile("cp.async.commit_group;" ::: "memory");
    };

    float acc[2][8][4];
    #pragma unroll
    for (int i = 0; i < 2; i++)
        #pragma unroll
        for (int j = 0; j < 8; j++)
            #pragma unroll
            for (int r = 0; r < 4; r++) acc[i][j][r] = 0.0f;

    issue_loads(0);

    for (int kc = 0; kc < NCHUNK2; kc++) {
        const int b = kc & 1;
        if (kc + 1 < NCHUNK2) {
            issue_loads(kc + 1);
            asm volatile("cp.async.wait_group 1;" ::: "memory");
        } else {
            asm volatile("cp.async.wait_group 0;" ::: "memory");
        }
        __syncthreads();

        #pragma unroll
        for (int ks = 0; ks < 2; ks++) {
            uint32_t afr[2][4];
            #pragma unroll
            for (int i = 0; i < 2; i++) {
                int row  = wm + i * 16 + (lane & 7) + ((lane >> 3) & 1) * 8;
                int half = lane >> 4;
                ldm_x4(afr[i], aBase[b] + row * (ASTRIDE * 2) + ks * 32 + half * 16);
            }
            uint32_t bfr[8][2];
            #pragma unroll
            for (int bj = 0; bj < 4; bj++) {
                int row  = wn + bj * 16 + (lane & 7) + (lane >> 4) * 8;
                int half = (lane >> 3) & 1;
                uint32_t q[4];
                ldm_x4(q, bBase[b] + row * (ASTRIDE * 2) + ks * 32 + half * 16);
                bfr[bj * 2][0] = q[0];     bfr[bj * 2][1] = q[1];
                bfr[bj * 2 + 1][0] = q[2]; bfr[bj * 2 + 1][1] = q[3];
            }
            #pragma unroll
            for (int i = 0; i < 2; i++)
                #pragma unroll
                for (int j = 0; j < 8; j++)
                    mma16816(acc[i][j], afr[i], bfr[j]);
        }
        __syncthreads();
    }

    const int gp   = lane >> 2;
    const int tid4 = lane & 3;
    #pragma unroll
    for (int j = 0; j < 8; j++) {
        const int n = n0 + wn + j * 8 + tid4 * 2;
        const float c0 = __ldg(&b2[n + 0]);
        const float c1 = __ldg(&b2[n + 1]);
        #pragma unroll
        for (int i = 0; i < 2; i++) {
            const int mrow = m0 + wm + i * 16 + gp;
            float2 v0, v1;
            v0.x = acc[i][j][0] + c0;
            v0.y = acc[i][j][1] + c1;
            v1.x = acc[i][j][2] + c0;
            v1.y = acc[i][j][3] + c1;
            *(float2*)&g_posPre[(size_t)mrow * E_ + n]       = v0;
            *(float2*)&g_posPre[(size_t)(mrow + 8) * E_ + n] = v1;
        }
    }
}

// ---------------- kernel 4: LayerNorm over posPre -> oPos, oNeg ------------
__global__ void __launch_bounds__(256)
ln_k(const float* __restrict__ gamma, const float* __restrict__ beta,
     float* __restrict__ oPos, float* __restrict__ oNeg)
{
    const int t    = blockIdx.x;
    const int tid  = threadIdx.x;
    const int lane = tid & 31;
    const int wid  = tid >> 5;
    __shared__ float rbuf[18];

    float2 v = ((const float2*)g_posPre)[(size_t)t * 256 + tid];

    float s_sum = v.x + v.y;
    float s_sq  = v.x * v.x + v.y * v.y;
    #pragma unroll
    for (int off = 16; off; off >>= 1) {
        s_sum += __shfl_xor_sync(0xffffffffu, s_sum, off);
        s_sq  += __shfl_xor_sync(0xffffffffu, s_sq,  off);
    }
    if (lane == 0) { rbuf[wid] = s_sum; rbuf[8 + wid] = s_sq; }
    __syncthreads();
    if (tid == 0) {
        float S = 0.f, S2 = 0.f;
        #pragma unroll
        for (int w = 0; w < 8; w++) { S += rbuf[w]; S2 += rbuf[8 + w]; }
        float mu  = S * (1.0f / E_);
        float var = S2 * (1.0f / E_) - mu * mu;
        rbuf[16] = mu;
        rbuf[17] = rsqrtf(var + LN_EPS);
    }
    __syncthreads();
    const float mu = rbuf[16], inv = rbuf[17];

    float2 gm = __ldg(&((const float2*)gamma)[tid]);
    float2 bt = __ldg(&((const float2*)beta)[tid]);
    float2 y;
    y.x = (v.x - mu) * inv * gm.x + bt.x;
    y.y = (v.y - mu) * inv * gm.y + bt.y;
    const size_t baseE2 = (size_t)t * 256;
    ((float2*)oPos)[baseE2 + tid] = y;
    ((float2*)oNeg)[baseE2 + tid] = y;
}

// ---------------- launcher (pure kernel launches; graph-capture safe) ------
extern "C" void kernel_launch(void* const* d_in, const int* in_sizes, int n_in,
                              void* d_out, int out_size)
{
    const float* x     = (const float*)d_in[0];
    const float* W1    = (const float*)d_in[1];
    const float* b1    = (const float*)d_in[2];
    const float* coff  = (const float*)d_in[3];
    const float* W2    = (const float*)d_in[4];
    const float* b2    = (const float*)d_in[5];
    const float* gam   = (const float*)d_in[6];
    const float* bet   = (const float*)d_in[7];
    const float* g1    = (const float*)d_in[8];
    const float* g2    = (const float*)d_in[9];
    const float* wI    = (const float*)d_in[10];
    const float* uI    = (const float*)d_in[11];

    float* out     = (float*)d_out;
    float* o_samp  = out;
    float* o_soft  = out + (size_t)TOK_ * C_;
    float* o_pos   = out + (size_t)2 * TOK_ * C_;
    float* o_neg   = o_pos + (size_t)TOK_ * E_;

    zero_k<<<1, 32>>>();
    split_x_k<<<(TOK_ * E_ / 4 + 255) / 256, 256>>>(x);
    split_w_k<<<(C_ * E_ / 4 + 255) / 256, 256>>>(W1);
    w2h_k<<<(E_ * C_ / 4 + 255) / 256, 256>>>(W2);
    gemm_mma<<<dim3(C_ / BN, TOK_ / BM), 256>>>(b1, coff);
    samp_k<<<NGRP / 256, 256>>>(g1, g2, wI, uI, o_samp, o_soft);
    refine_k<<<256, 256>>>(g1, g2, wI, uI, x, W1, b1, coff, o_samp);
    gemm2_mma<<<dim3(E_ / BN, TOK_ / BM), 256>>>(b2);
    ln_k<<<TOK_, 256>>>(gam, bet, o_pos, o_neg);
}